// round 16
// baseline (speedup 1.0000x reference)
#include <cuda_runtime.h>
#include <cuda_fp16.h>

// ---------------- problem constants ----------------
#define B_      16
#define C_      256
#define HEADS_  8
#define D_      32          // dim_head
#define HW_     4096        // 64*64
#define W_      64
#define LN_EPS  1e-5f

// ---------------- scratch (no allocations allowed) ----------------
__device__ __half  g_wqh[3 * C_ * C_];                    // w_qkv fp16
__device__ __half2 g_xh[(size_t)B_ * 128 * HW_];          // x packed [b][c2][p]
__device__ __half2 g_q2[(size_t)B_ * 128 * HW_];          // qhat packed [b][c2][p]
__device__ float   g_ctxp[(size_t)B_ * HEADS_ * 32 * (D_ * D_)];
__device__ __half  g_weffh[(size_t)B_ * C_ * C_];         // w_eff fp16

// ---------------- helpers ----------------
__device__ __forceinline__ unsigned h2u(__half2 h) { return *(unsigned*)&h; }

__device__ __forceinline__ void mma_f16(float* c, const unsigned* a, const unsigned* b) {
    asm volatile(
        "mma.sync.aligned.m16n8k16.row.col.f32.f16.f16.f32 "
        "{%0,%1,%2,%3}, {%4,%5,%6,%7}, {%8,%9}, {%0,%1,%2,%3};"
        : "+f"(c[0]), "+f"(c[1]), "+f"(c[2]), "+f"(c[3])
        : "r"(a[0]), "r"(a[1]), "r"(a[2]), "r"(a[3]), "r"(b[0]), "r"(b[1]));
}

__device__ __forceinline__ void ldsm_x4(unsigned* r, unsigned saddr) {
    asm volatile("ldmatrix.sync.aligned.m8n8.x4.shared.b16 {%0,%1,%2,%3}, [%4];"
        : "=r"(r[0]), "=r"(r[1]), "=r"(r[2]), "=r"(r[3]) : "r"(saddr));
}

__device__ __forceinline__ unsigned s2u(const void* p) {
    return (unsigned)__cvta_generic_to_shared(p);
}
__device__ __forceinline__ void cp16s(unsigned sdst, const void* gsrc) {
    asm volatile("cp.async.cg.shared.global [%0], [%1], 16;" :: "r"(sdst), "l"(gsrc));
}
#define CP_COMMIT()  asm volatile("cp.async.commit_group;")
#define CP_WAIT(n)   asm volatile("cp.async.wait_group %0;" :: "n"(n))

// ---------------- dynamic smem layouts (3-stage pipelines) ----------------
#define A_STRIDE_B  80    // 40 halves per row
struct MainSmem {
    union {
        struct {
            __half  As[3][128][40];    // [m][k] halves; LDSM rows conflict-free
            __half2 Bs[3][16][136];    // [k2][pixel] chan-pairs, pad 136 -> 8tg+g
        } ld;
        float P[8][32][33];            // per-warp ctx partials (dead-As/Bs overlay)
    } u;
    __half sc[128][136];               // [row][pixel] khat|v halves
    float red[2][4][64];               // k-softmax cross-warp partials
};
struct OutSmem {                       // M=256 x N=128 tile, 16 warps
    __half  As[3][256][40];
    __half2 Bs[3][16][136];
    float s_sum[128], s_sq[128], s_mu[128], s_rs[128];
};

// =====================================================================
// Kernel 0 (merged): bid < 8192 -> pack x; else -> convert w_qkv.
// =====================================================================
__global__ void __launch_bounds__(256) k_pre(const float* __restrict__ x,
                                             const float* __restrict__ w) {
    unsigned bid = blockIdx.x;
    if (bid < 8192) {
        unsigned i = bid * 256 + threadIdx.x;        // (b, c2, p4)
        int p4 = i & 1023;
        int c2 = (i >> 10) & 127;
        int b  = i >> 17;
        const float4 v0 = *(const float4*)&x[((size_t)b * C_ + 2 * c2)     * HW_ + p4 * 4];
        const float4 v1 = *(const float4*)&x[((size_t)b * C_ + 2 * c2 + 1) * HW_ + p4 * 4];
        __half2* dst = &g_xh[((size_t)b * 128 + c2) * HW_ + p4 * 4];
        dst[0] = __floats2half2_rn(v0.x, v1.x);
        dst[1] = __floats2half2_rn(v0.y, v1.y);
        dst[2] = __floats2half2_rn(v0.z, v1.z);
        dst[3] = __floats2half2_rn(v0.w, v1.w);
    } else {
        unsigned i = (bid - 8192) * 256 + threadIdx.x;
        float4 v = ((const float4*)w)[i];
        __half2* dst = (__half2*)&g_wqh[(size_t)i * 4];
        dst[0] = __floats2half2_rn(v.x, v.y);
        dst[1] = __floats2half2_rn(v.z, v.w);
    }
}

// =====================================================================
// Kernel 1 (MERGED): bid < 1024 -> q path; bid >= 1024 -> kv+ctx path.
// fp16 m16n8k16, 128x128x256 tiles, 8 warps (2x4), fp32 accumulate.
// A via ldmatrix.x4; B via scalar half2 loads. 3-stage cp.async pipeline,
// single __syncthreads per k-iteration.
// =====================================================================
__global__ void __launch_bounds__(256) k_main() {
    extern __shared__ char smem_raw[];
    MainSmem& S = *reinterpret_cast<MainSmem*>(smem_raw);

    const int tid  = threadIdx.x;
    const int warp = tid >> 5, lane = tid & 31;
    const int g = lane >> 2, tg = lane & 3;
    const int wm = warp >> 2, wn = warp & 3;

    const int bid = blockIdx.x;
    const bool isQ = bid < 1024;
    int m0 = 0, b, p0, hp = 0, pt = 0;
    if (isQ) {
        m0 = (bid >> 9) * 128;
        int t = bid & 511;
        b  = t >> 5;
        p0 = (t & 31) * 128;
    } else {
        int k2 = bid - 1024;
        hp = k2 & 3;
        pt = (k2 >> 2) & 31;
        b  = k2 >> 7;
        p0 = pt * 128;
    }

    // hoisted pointers: A (w rows, halves), B (g_xh half2)
    const __half* pa[2]; const __half2* pb[2];
    unsigned sa[3][2], sb[3][2];
#pragma unroll
    for (int i = 0; i < 2; i++) {
        int f4 = tid + i * 256;
        int ra = f4 >> 2, ca = (f4 & 3) * 8;         // 128 rows x 32 halves
        int gr = isQ ? (m0 + ra)
                     : ((ra < 64) ? (C_ + hp * 64 + ra) : (2 * C_ + hp * 64 + ra - 64));
        pa[i] = g_wqh + (size_t)gr * C_ + ca;
        int rb = f4 >> 5, cb = (f4 & 31) * 4;        // 16 c2-rows x 128 half2
        pb[i] = g_xh + ((size_t)b * 128 + rb) * HW_ + p0 + cb;
#pragma unroll
        for (int s = 0; s < 3; s++) {
            sa[s][i] = s2u(&S.u.ld.As[s][ra][ca]);
            sb[s][i] = s2u(&S.u.ld.Bs[s][rb][cb]);
        }
    }

    // ldmatrix per-lane base addresses
    const int lmRow = wm * 64 + (lane & 15);
    const int lmCol = (lane >> 4) * 8;
    unsigned baseA[3];
#pragma unroll
    for (int s = 0; s < 3; s++) baseA[s] = s2u(&S.u.ld.As[s][lmRow][lmCol]);

    float acc[4][4][4] = {};

    // prologue: stages 0, 1
#pragma unroll
    for (int s = 0; s < 2; s++) {
#pragma unroll
        for (int i = 0; i < 2; i++) {
            cp16s(sa[s][i], pa[i]);  pa[i] += 32;
            cp16s(sb[s][i], pb[i]);  pb[i] += 16 * HW_;
        }
        CP_COMMIT();
    }

#pragma unroll
    for (int it = 0; it < 8; it++) {
        if (it < 7) { CP_WAIT(1); } else { CP_WAIT(0); }
        __syncthreads();
        if (it < 6) {
            const int st = (it + 2) % 3;
#pragma unroll
            for (int i = 0; i < 2; i++) {
                cp16s(sa[st][i], pa[i]);  pa[i] += 32;
                cp16s(sb[st][i], pb[i]);  pb[i] += 16 * HW_;
            }
            CP_COMMIT();
        }
        const int bu = it % 3;
#pragma unroll
        for (int ks = 0; ks < 2; ks++) {
            unsigned af[4][4], bf[4][2];
#pragma unroll
            for (int mt = 0; mt < 4; mt++)
                ldsm_x4(af[mt], baseA[bu] + mt * (16 * A_STRIDE_B) + ks * 32);
#pragma unroll
            for (int nt = 0; nt < 4; nt++) {
                int cn = wn * 32 + nt * 8 + g;
                bf[nt][0] = h2u(S.u.ld.Bs[bu][ks * 8 + tg][cn]);
                bf[nt][1] = h2u(S.u.ld.Bs[bu][ks * 8 + tg + 4][cn]);
            }
#pragma unroll
            for (int mt = 0; mt < 4; mt++)
#pragma unroll
                for (int nt = 0; nt < 4; nt++)
                    mma_f16(acc[mt][nt], af[mt], bf[nt]);
        }
    }

    if (isQ) {
        // ---- q-softmax over d=32 (head = mt-pair; rows span g via shfl)
#pragma unroll
        for (int p = 0; p < 2; p++) {
#pragma unroll
            for (int nt = 0; nt < 4; nt++) {
#pragma unroll
                for (int j = 0; j < 2; j++) {
                    float v0 = acc[2 * p][nt][j],     v1 = acc[2 * p][nt][j + 2];
                    float v2 = acc[2 * p + 1][nt][j], v3 = acc[2 * p + 1][nt][j + 2];
                    float m = fmaxf(fmaxf(v0, v1), fmaxf(v2, v3));
                    m = fmaxf(m, __shfl_xor_sync(0xffffffffu, m, 4));
                    m = fmaxf(m, __shfl_xor_sync(0xffffffffu, m, 8));
                    m = fmaxf(m, __shfl_xor_sync(0xffffffffu, m, 16));
                    float e0 = __expf(v0 - m), e1 = __expf(v1 - m);
                    float e2 = __expf(v2 - m), e3 = __expf(v3 - m);
                    float s = e0 + e1 + e2 + e3;
                    s += __shfl_xor_sync(0xffffffffu, s, 4);
                    s += __shfl_xor_sync(0xffffffffu, s, 8);
                    s += __shfl_xor_sync(0xffffffffu, s, 16);
                    float inv = 1.0f / s;
                    acc[2 * p][nt][j]         = e0 * inv;
                    acc[2 * p][nt][j + 2]     = e1 * inv;
                    acc[2 * p + 1][nt][j]     = e2 * inv;
                    acc[2 * p + 1][nt][j + 2] = e3 * inv;
                }
            }
        }
        // ---- paired fp16 store: channel pairs (r0, r0+1) via shfl_xor(4)
#pragma unroll
        for (int mt = 0; mt < 4; mt++) {
            int r0 = m0 + wm * 64 + mt * 16 + g;
#pragma unroll
            for (int nt = 0; nt < 4; nt++) {
                float o0 = acc[mt][nt][0], o1 = acc[mt][nt][1];
                float o2 = acc[mt][nt][2], o3 = acc[mt][nt][3];
                float q0 = __shfl_xor_sync(0xffffffffu, o0, 4);
                float q1 = __shfl_xor_sync(0xffffffffu, o1, 4);
                float q2 = __shfl_xor_sync(0xffffffffu, o2, 4);
                float q3 = __shfl_xor_sync(0xffffffffu, o3, 4);
                if (!(g & 1)) {
                    int c = wn * 32 + nt * 8 + tg * 2;
                    __half2* d0 = &g_q2[((size_t)b * 128 + (r0 >> 1)) * HW_ + p0 + c];
                    d0[0] = __floats2half2_rn(o0, q0);
                    d0[1] = __floats2half2_rn(o1, q1);
                    __half2* d1 = d0 + (size_t)4 * HW_;     // rows r0+8, r0+9
                    d1[0] = __floats2half2_rn(o2, q2);
                    d1[1] = __floats2half2_rn(o3, q3);
                }
            }
        }
        return;
    }

    // ================= kv path =================
    // ---- k-softmax over y=64 (rows 0-63 -> wm==0 warps)
    float mloc[4][2], sloc[4][2];
    if (wm == 0) {
#pragma unroll
        for (int mt = 0; mt < 4; mt++)
#pragma unroll
            for (int hf = 0; hf < 2; hf++) {
                float m = -1e30f;
#pragma unroll
                for (int nt = 0; nt < 4; nt++) {
                    m = fmaxf(m, acc[mt][nt][hf * 2]);
                    m = fmaxf(m, acc[mt][nt][hf * 2 + 1]);
                }
                m = fmaxf(m, __shfl_xor_sync(0xffffffffu, m, 1));
                m = fmaxf(m, __shfl_xor_sync(0xffffffffu, m, 2));
                mloc[mt][hf] = m;
                if (tg == 0) S.red[0][wn][mt * 16 + hf * 8 + g] = m;
            }
    }
    __syncthreads();
    if (wm == 0) {
#pragma unroll
        for (int mt = 0; mt < 4; mt++)
#pragma unroll
            for (int hf = 0; hf < 2; hf++) {
                int ri = mt * 16 + hf * 8 + g;
                float m = fmaxf(mloc[mt][hf], S.red[0][wn ^ 1][ri]);
                float s = 0.f;
#pragma unroll
                for (int nt = 0; nt < 4; nt++) {
                    float e0 = __expf(acc[mt][nt][hf * 2] - m);
                    float e1 = __expf(acc[mt][nt][hf * 2 + 1] - m);
                    acc[mt][nt][hf * 2]     = e0;
                    acc[mt][nt][hf * 2 + 1] = e1;
                    s += e0 + e1;
                }
                s += __shfl_xor_sync(0xffffffffu, s, 1);
                s += __shfl_xor_sync(0xffffffffu, s, 2);
                sloc[mt][hf] = s;
                if (tg == 0) S.red[1][wn][ri] = s;
            }
    }
    __syncthreads();
    if (wm == 0) {
#pragma unroll
        for (int mt = 0; mt < 4; mt++)
#pragma unroll
            for (int hf = 0; hf < 2; hf++) {
                int ri = mt * 16 + hf * 8 + g;
                float inv = 1.0f / (sloc[mt][hf] + S.red[1][wn ^ 1][ri]);
#pragma unroll
                for (int nt = 0; nt < 4; nt++) {
                    acc[mt][nt][hf * 2]     *= inv;
                    acc[mt][nt][hf * 2 + 1] *= inv;
                }
            }
    }
    __syncthreads();

    // ---- store sc[row][pixel] as fp16 (half2 per pixel pair)
#pragma unroll
    for (int mt = 0; mt < 4; mt++) {
        int r0 = wm * 64 + mt * 16 + g;
#pragma unroll
        for (int nt = 0; nt < 4; nt++) {
            int c = wn * 32 + nt * 8 + tg * 2;
            *(__half2*)&S.sc[r0][c]     = __floats2half2_rn(acc[mt][nt][0], acc[mt][nt][1]);
            *(__half2*)&S.sc[r0 + 8][c] = __floats2half2_rn(acc[mt][nt][2], acc[mt][nt][3]);
        }
    }
    __syncthreads();

    // ---- ctx partial via fp16 MMA: per warp M=32(d) x N=32(e) x K=32(p)
    {
        const int h  = warp >> 2, hb = h * 32;
        const int pb0 = (warp & 3) * 32;
        float cacc[2][4][4] = {};
#pragma unroll
        for (int ks = 0; ks < 2; ks++) {
            const int pw = pb0 + ks * 16;
            unsigned af[2][4], bf[4][2];
#pragma unroll
            for (int mt = 0; mt < 2; mt++) {
                int dm = hb + mt * 16 + g;
                af[mt][0] = *(const unsigned*)&S.sc[dm][pw + 2 * tg];
                af[mt][1] = *(const unsigned*)&S.sc[dm + 8][pw + 2 * tg];
                af[mt][2] = *(const unsigned*)&S.sc[dm][pw + 2 * tg + 8];
                af[mt][3] = *(const unsigned*)&S.sc[dm + 8][pw + 2 * tg + 8];
            }
#pragma unroll
            for (int nt = 0; nt < 4; nt++) {
                int en = 64 + hb + nt * 8 + g;
                bf[nt][0] = *(const unsigned*)&S.sc[en][pw + 2 * tg];
                bf[nt][1] = *(const unsigned*)&S.sc[en][pw + 2 * tg + 8];
            }
#pragma unroll
            for (int mt = 0; mt < 2; mt++)
#pragma unroll
                for (int nt = 0; nt < 4; nt++)
                    mma_f16(cacc[mt][nt], af[mt], bf[nt]);
        }
#pragma unroll
        for (int mt = 0; mt < 2; mt++) {
            int d = mt * 16 + g;
#pragma unroll
            for (int nt = 0; nt < 4; nt++) {
                int e = nt * 8 + tg * 2;
                S.u.P[warp][d][e]         = cacc[mt][nt][0];
                S.u.P[warp][d][e + 1]     = cacc[mt][nt][1];
                S.u.P[warp][d + 8][e]     = cacc[mt][nt][2];
                S.u.P[warp][d + 8][e + 1] = cacc[mt][nt][3];
            }
        }
    }
    __syncthreads();

    // ---- reduce 4 K-slices per head, write ctx partial
    {
        float* op = g_ctxp + (((size_t)(b * HEADS_ + hp * 2)) * 32 + pt) * (D_ * D_);
#pragma unroll
        for (int i = 0; i < 8; i++) {
            int elem = tid + i * 256;
            int hh = elem >> 10;
            int de = elem & 1023;
            int d = de >> 5, e = de & 31;
            float s = S.u.P[hh * 4 + 0][d][e] + S.u.P[hh * 4 + 1][d][e]
                    + S.u.P[hh * 4 + 2][d][e] + S.u.P[hh * 4 + 3][d][e];
            op[(size_t)hh * 32 * (D_ * D_) + de] = s;
        }
    }
}

// =====================================================================
// Kernel 2: reduce ctx partials + w_eff = w_out @ ctx -> fp16.
// grid (8 heads, 16 batches, 2 e-halves), 256 threads — 2x block-level
// memory parallelism on the latency-bound partial reduction; per-element
// summation order unchanged (bit-identical result).
// =====================================================================
__global__ void __launch_bounds__(256) k_weff(const float* __restrict__ w_out) {
    const int h  = blockIdx.x, b = blockIdx.y;
    const int eh = blockIdx.z;            // e-half: columns eh*16 .. eh*16+15
    const int bh = b * HEADS_ + h;
    const int e0 = eh * 16;
    const int t  = threadIdx.x;

    __shared__ float ctxs[32][20];        // [d][e-half], pad 20
    __shared__ float ws[256][33];

    // reduce this block's e-slice of the 32 partials: elem = (d, ec pair)
    {
        const float* base = g_ctxp + (size_t)bh * 32 * (D_ * D_) + e0;
        const int d  = t >> 3;            // 0..31
        const int ec = (t & 7) * 2;       // 0..14
        const float2* src = (const float2*)(base + d * 32 + ec);
        float2 s0 = make_float2(0.f, 0.f), s1 = s0, s2 = s0, s3 = s0;
#pragma unroll
        for (int pg = 0; pg < 32; pg += 4) {
            float2 v0 = src[(pg + 0) * 512];   // 1024 floats = 512 float2 per partial
            float2 v1 = src[(pg + 1) * 512];
            float2 v2 = src[(pg + 2) * 512];
            float2 v3 = src[(pg + 3) * 512];
            s0.x += v0.x; s0.y += v0.y;
            s1.x += v1.x; s1.y += v1.y;
            s2.x += v2.x; s2.y += v2.y;
            s3.x += v3.x; s3.y += v3.y;
        }
        float2 s = make_float2(s0.x + s1.x + s2.x + s3.x, s0.y + s1.y + s2.y + s3.y);
        *(float2*)&ctxs[d][ec] = s;
    }
#pragma unroll
    for (int i = 0; i < 32; i++) {
        int idx = t + i * 256;
        int r = idx >> 5, c = idx & 31;
        ws[r][c] = w_out[(size_t)r * C_ + h * D_ + c];
    }
    __syncthreads();

    float we[16] = {};
#pragma unroll
    for (int d = 0; d < 32; d++) {
        float wv = ws[t][d];
#pragma unroll
        for (int e = 0; e < 16; e++) we[e] += wv * ctxs[d][e];
    }
    __half* op = g_weffh + ((size_t)b * C_ + t) * C_ + h * D_ + e0;
#pragma unroll
    for (int e2 = 0; e2 < 8; e2++)
        *(__half2*)&op[e2 * 2] = __floats2half2_rn(we[e2 * 2], we[e2 * 2 + 1]);
}

// =====================================================================
// Kernel 3: out = w_eff[b] @ qhat + b_out, fused channel LayerNorm.
// fp16 MMA; M=256 x N=128 tile, 512 threads (16 warps 4x4); 3-stage pipe.
// =====================================================================
__global__ void __launch_bounds__(512) k_out_ln(const float* __restrict__ b_out,
                                                const float* __restrict__ gamma,
                                                const float* __restrict__ beta,
                                                float* __restrict__ out) {
    extern __shared__ char smem_raw[];
    OutSmem& S = *reinterpret_cast<OutSmem*>(smem_raw);

    const int tid  = threadIdx.x;
    const int warp = tid >> 5, lane = tid & 31;
    const int g = lane >> 2, tg = lane & 3;
    const int wm = warp >> 2, wn = warp & 3;     // 4 x 4 warp grid

    const int blk = blockIdx.x;
    const int b   = blk >> 5;                    // 32 pixel-tiles per batch
    const int p0  = (blk & 31) * 128;

    if (tid < 128) { S.s_sum[tid] = 0.f; S.s_sq[tid] = 0.f; }

    const __half* pa[2]; const __half2* pb;
    unsigned sa[3][2], sb[3];
#pragma unroll
    for (int i = 0; i < 2; i++) {
        int f4 = tid + i * 512;
        int ra = f4 >> 2, ca = (f4 & 3) * 8;
        pa[i] = g_weffh + (size_t)b * C_ * C_ + (size_t)ra * C_ + ca;
#pragma unroll
        for (int s = 0; s < 3; s++) sa[s][i] = s2u(&S.As[s][ra][ca]);
    }
    {
        int rb = tid >> 5, cb = (tid & 31) * 4;
        pb = g_q2 + ((size_t)b * 128 + rb) * HW_ + p0 + cb;
#pragma unroll
        for (int s = 0; s < 3; s++) sb[s] = s2u(&S.Bs[s][rb][cb]);
    }

    const int lmRow = wm * 64 + (lane & 15);
    const int lmCol = (lane >> 4) * 8;
    unsigned baseA[3];
#pragma unroll
    for (int s = 0; s < 3; s++) baseA[s] = s2u(&S.As[s][lmRow][lmCol]);

    float acc[4][4][4] = {};

#pragma unroll
    for (int s = 0; s < 2; s++) {
#pragma unroll
        for (int i = 0; i < 2; i++) { cp16s(sa[s][i], pa[i]); pa[i] += 32; }
        cp16s(sb[s], pb); pb += 16 * HW_;
        CP_COMMIT();
    }

#pragma unroll
    for (int it = 0; it < 8; it++) {
        if (it < 7) { CP_WAIT(1); } else { CP_WAIT(0); }
        __syncthreads();
        if (it < 6) {
            const int st = (it + 2) % 3;
#pragma unroll
            for (int i = 0; i < 2; i++) { cp16s(sa[st][i], pa[i]); pa[i] += 32; }
            cp16s(sb[st], pb); pb += 16 * HW_;
            CP_COMMIT();
        }
        const int bu = it % 3;
#pragma unroll
        for (int ks = 0; ks < 2; ks++) {
            unsigned af[4][4], bf[4][2];
#pragma unroll
            for (int mt = 0; mt < 4; mt++)
                ldsm_x4(af[mt], baseA[bu] + mt * (16 * A_STRIDE_B) + ks * 32);
#pragma unroll
            for (int nt = 0; nt < 4; nt++) {
                int cn = wn * 32 + nt * 8 + g;
                bf[nt][0] = h2u(S.Bs[bu][ks * 8 + tg][cn]);
                bf[nt][1] = h2u(S.Bs[bu][ks * 8 + tg + 4][cn]);
            }
#pragma unroll
            for (int mt = 0; mt < 4; mt++)
#pragma unroll
                for (int nt = 0; nt < 4; nt++)
                    mma_f16(acc[mt][nt], af[mt], bf[nt]);
        }
    }

    float bias0[4], bias1[4], gam0[4], gam1[4], bet0[4], bet1[4];
#pragma unroll
    for (int mt = 0; mt < 4; mt++) {
        int r = wm * 64 + mt * 16 + g;
        bias0[mt] = b_out[r]; bias1[mt] = b_out[r + 8];
        gam0[mt]  = gamma[r]; gam1[mt]  = gamma[r + 8];
        bet0[mt]  = beta[r];  bet1[mt]  = beta[r + 8];
    }
#pragma unroll
    for (int mt = 0; mt < 4; mt++)
#pragma unroll
        for (int nt = 0; nt < 4; nt++) {
            acc[mt][nt][0] += bias0[mt]; acc[mt][nt][1] += bias0[mt];
            acc[mt][nt][2] += bias1[mt]; acc[mt][nt][3] += bias1[mt];
        }

#pragma unroll
    for (int nt = 0; nt < 4; nt++) {
        float s0 = 0.f, s1 = 0.f, q0 = 0.f, q1 = 0.f;
#pragma unroll
        for (int mt = 0; mt < 4; mt++) {
            float v0 = acc[mt][nt][0], v1 = acc[mt][nt][1];
            float v2 = acc[mt][nt][2], v3 = acc[mt][nt][3];
            s0 += v0 + v2; s1 += v1 + v3;
            q0 += v0 * v0 + v2 * v2; q1 += v1 * v1 + v3 * v3;
        }
#pragma unroll
        for (int off = 4; off < 32; off <<= 1) {
            s0 += __shfl_xor_sync(0xffffffffu, s0, off);
            s1 += __shfl_xor_sync(0xffffffffu, s1, off);
            q0 += __shfl_xor_sync(0xffffffffu, q0, off);
            q1 += __shfl_xor_sync(0xffffffffu, q1, off);
        }
        if (g == 0) {
            int c = wn * 32 + nt * 8 + tg * 2;
            atomicAdd(&S.s_sum[c], s0);     atomicAdd(&S.s_sq[c], q0);
            atomicAdd(&S.s_sum[c + 1], s1); atomicAdd(&S.s_sq[c + 1], q1);
        }
    }
    __syncthreads();

    if (tid < 128) {
        float mu  = S.s_sum[tid] * (1.0f / 256.0f);
        float var = S.s_sq[tid] * (1.0f / 256.0f) - mu * mu;
        S.s_mu[tid] = mu;
        S.s_rs[tid] = rsqrtf(var + LN_EPS);
    }
    __syncthreads();

    float* ob = out + (size_t)b * (C_ * HW_) + p0;
#pragma unroll
    for (int mt = 0; mt < 4; mt++) {
        int r = wm * 64 + mt * 16 + g;
#pragma unroll
        for (int nt = 0; nt < 4; nt++) {
            int c = wn * 32 + nt * 8 + tg * 2;
            float mu0 = S.s_mu[c], rs0 = S.s_rs[c];
            float mu1 = S.s_mu[c + 1], rs1 = S.s_rs[c + 1];
            float o0 = (acc[mt][nt][0] - mu0) * rs0 * gam0[mt] + bet0[mt];
            float o1 = (acc[mt][nt][1] - mu1) * rs1 * gam0[mt] + bet0[mt];
            float o2 = (acc[mt][nt][2] - mu0) * rs0 * gam1[mt] + bet1[mt];
            float o3 = (acc[mt][nt][3] - mu1) * rs1 * gam1[mt] + bet1[mt];
            *(float2*)&ob[(size_t)r * HW_ + c]       = make_float2(o0, o1);
            *(float2*)&ob[(size_t)(r + 8) * HW_ + c] = make_float2(o2, o3);
        }
    }
}

// =====================================================================
extern "C" void kernel_launch(void* const* d_in, const int* in_sizes, int n_in,
                              void* d_out, int out_size) {
    const float* x      = (const float*)d_in[0];
    const float* w_qkv  = (const float*)d_in[1];
    const float* w_out  = (const float*)d_in[2];
    const float* b_out  = (const float*)d_in[3];
    const float* gamma  = (const float*)d_in[4];
    const float* beta   = (const float*)d_in[5];
    float* out = (float*)d_out;

    cudaFuncSetAttribute(k_main, cudaFuncAttributeMaxDynamicSharedMemorySize,
                         (int)sizeof(MainSmem));
    cudaFuncSetAttribute(k_out_ln, cudaFuncAttributeMaxDynamicSharedMemorySize,
                         (int)sizeof(OutSmem));

    k_pre<<<8192 + 192, 256>>>(x, w_qkv);                 // x pack + w convert

    k_main<<<1024 + 2048, 256, sizeof(MainSmem)>>>();     // q blocks, then kv

    dim3 g3(HEADS_, B_, 2);                               // 8 x 16 x 2 e-halves
    k_weff<<<g3, 256>>>(w_out);

    k_out_ln<<<(B_ * HW_) / 128, 512, sizeof(OutSmem)>>>(b_out, gamma, beta, out);
}

// round 17
// speedup vs baseline: 1.0216x; 1.0216x over previous
#include <cuda_runtime.h>
#include <cuda_fp16.h>

// ---------------- problem constants ----------------
#define B_      16
#define C_      256
#define HEADS_  8
#define D_      32          // dim_head
#define HW_     4096        // 64*64
#define W_      64
#define LN_EPS  1e-5f

// ---------------- scratch (no allocations allowed) ----------------
__device__ __half  g_wqh[3 * C_ * C_];                    // w_qkv fp16
__device__ __half2 g_xh[(size_t)B_ * 128 * HW_];          // x packed [b][c2][p]
__device__ __half2 g_q2[(size_t)B_ * 128 * HW_];          // qhat packed [b][c2][p]
__device__ float   g_ctxp[(size_t)B_ * HEADS_ * 32 * (D_ * D_)];
__device__ __half  g_weffh[(size_t)B_ * C_ * C_];         // w_eff fp16

// ---------------- helpers ----------------
__device__ __forceinline__ unsigned h2u(__half2 h) { return *(unsigned*)&h; }

__device__ __forceinline__ void mma_f16(float* c, const unsigned* a, const unsigned* b) {
    asm volatile(
        "mma.sync.aligned.m16n8k16.row.col.f32.f16.f16.f32 "
        "{%0,%1,%2,%3}, {%4,%5,%6,%7}, {%8,%9}, {%0,%1,%2,%3};"
        : "+f"(c[0]), "+f"(c[1]), "+f"(c[2]), "+f"(c[3])
        : "r"(a[0]), "r"(a[1]), "r"(a[2]), "r"(a[3]), "r"(b[0]), "r"(b[1]));
}

__device__ __forceinline__ void ldsm_x4(unsigned* r, unsigned saddr) {
    asm volatile("ldmatrix.sync.aligned.m8n8.x4.shared.b16 {%0,%1,%2,%3}, [%4];"
        : "=r"(r[0]), "=r"(r[1]), "=r"(r[2]), "=r"(r[3]) : "r"(saddr));
}

__device__ __forceinline__ unsigned s2u(const void* p) {
    return (unsigned)__cvta_generic_to_shared(p);
}
__device__ __forceinline__ void cp16s(unsigned sdst, const void* gsrc) {
    asm volatile("cp.async.cg.shared.global [%0], [%1], 16;" :: "r"(sdst), "l"(gsrc));
}
#define CP_COMMIT()  asm volatile("cp.async.commit_group;")
#define CP_WAIT(n)   asm volatile("cp.async.wait_group %0;" :: "n"(n))

// ---------------- dynamic smem layouts (3-stage pipelines) ----------------
#define A_STRIDE_B  80    // 40 halves per row
struct MainSmem {
    union {
        struct {
            __half  As[3][128][40];    // [m][k] halves; LDSM rows conflict-free
            __half2 Bs[3][16][136];    // [k2][pixel] chan-pairs, pad 136 -> 8tg+g
        } ld;
        float P[8][32][33];            // per-warp ctx partials (dead-As/Bs overlay)
    } u;
    __half sc[128][136];               // [row][pixel] khat|v halves
    float red[2][4][64];               // k-softmax cross-warp partials
};
struct OutSmem {                       // M=256 x N=128 tile, 16 warps
    __half  As[3][256][40];
    __half2 Bs[3][16][136];
    float s_sum[128], s_sq[128], s_mu[128], s_rs[128];
};

// =====================================================================
// Kernel 0 (merged): bid < 8192 -> pack x; else -> convert w_qkv.
// =====================================================================
__global__ void __launch_bounds__(256) k_pre(const float* __restrict__ x,
                                             const float* __restrict__ w) {
    unsigned bid = blockIdx.x;
    if (bid < 8192) {
        unsigned i = bid * 256 + threadIdx.x;        // (b, c2, p4)
        int p4 = i & 1023;
        int c2 = (i >> 10) & 127;
        int b  = i >> 17;
        const float4 v0 = *(const float4*)&x[((size_t)b * C_ + 2 * c2)     * HW_ + p4 * 4];
        const float4 v1 = *(const float4*)&x[((size_t)b * C_ + 2 * c2 + 1) * HW_ + p4 * 4];
        __half2* dst = &g_xh[((size_t)b * 128 + c2) * HW_ + p4 * 4];
        dst[0] = __floats2half2_rn(v0.x, v1.x);
        dst[1] = __floats2half2_rn(v0.y, v1.y);
        dst[2] = __floats2half2_rn(v0.z, v1.z);
        dst[3] = __floats2half2_rn(v0.w, v1.w);
    } else {
        unsigned i = (bid - 8192) * 256 + threadIdx.x;
        float4 v = ((const float4*)w)[i];
        __half2* dst = (__half2*)&g_wqh[(size_t)i * 4];
        dst[0] = __floats2half2_rn(v.x, v.y);
        dst[1] = __floats2half2_rn(v.z, v.w);
    }
}

// =====================================================================
// Kernel 1 (MERGED): bid < 2048 -> kv+ctx path (long epilogue, FIRST);
//                    bid >= 2048 -> q path (short epilogue, tail wave).
// fp16 m16n8k16, 128x128x256 tiles, 8 warps (2x4), fp32 accumulate.
// A via ldmatrix.x4; B via scalar half2 loads. 3-stage cp.async pipeline,
// single __syncthreads per k-iteration.
// =====================================================================
__global__ void __launch_bounds__(256) k_main() {
    extern __shared__ char smem_raw[];
    MainSmem& S = *reinterpret_cast<MainSmem*>(smem_raw);

    const int tid  = threadIdx.x;
    const int warp = tid >> 5, lane = tid & 31;
    const int g = lane >> 2, tg = lane & 3;
    const int wm = warp >> 2, wn = warp & 3;

    const int bid = blockIdx.x;
    const bool isQ = bid >= 2048;                // kv blocks first
    int m0 = 0, b, p0, hp = 0, pt = 0;
    if (isQ) {
        int qb = bid - 2048;
        m0 = (qb >> 9) * 128;
        int t = qb & 511;
        b  = t >> 5;
        p0 = (t & 31) * 128;
    } else {
        hp = bid & 3;
        pt = (bid >> 2) & 31;
        b  = bid >> 7;
        p0 = pt * 128;
    }

    // hoisted pointers: A (w rows, halves), B (g_xh half2)
    const __half* pa[2]; const __half2* pb[2];
    unsigned sa[3][2], sb[3][2];
#pragma unroll
    for (int i = 0; i < 2; i++) {
        int f4 = tid + i * 256;
        int ra = f4 >> 2, ca = (f4 & 3) * 8;         // 128 rows x 32 halves
        int gr = isQ ? (m0 + ra)
                     : ((ra < 64) ? (C_ + hp * 64 + ra) : (2 * C_ + hp * 64 + ra - 64));
        pa[i] = g_wqh + (size_t)gr * C_ + ca;
        int rb = f4 >> 5, cb = (f4 & 31) * 4;        // 16 c2-rows x 128 half2
        pb[i] = g_xh + ((size_t)b * 128 + rb) * HW_ + p0 + cb;
#pragma unroll
        for (int s = 0; s < 3; s++) {
            sa[s][i] = s2u(&S.u.ld.As[s][ra][ca]);
            sb[s][i] = s2u(&S.u.ld.Bs[s][rb][cb]);
        }
    }

    // ldmatrix per-lane base addresses
    const int lmRow = wm * 64 + (lane & 15);
    const int lmCol = (lane >> 4) * 8;
    unsigned baseA[3];
#pragma unroll
    for (int s = 0; s < 3; s++) baseA[s] = s2u(&S.u.ld.As[s][lmRow][lmCol]);

    float acc[4][4][4] = {};

    // prologue: stages 0, 1
#pragma unroll
    for (int s = 0; s < 2; s++) {
#pragma unroll
        for (int i = 0; i < 2; i++) {
            cp16s(sa[s][i], pa[i]);  pa[i] += 32;
            cp16s(sb[s][i], pb[i]);  pb[i] += 16 * HW_;
        }
        CP_COMMIT();
    }

#pragma unroll
    for (int it = 0; it < 8; it++) {
        if (it < 7) { CP_WAIT(1); } else { CP_WAIT(0); }
        __syncthreads();
        if (it < 6) {
            const int st = (it + 2) % 3;
#pragma unroll
            for (int i = 0; i < 2; i++) {
                cp16s(sa[st][i], pa[i]);  pa[i] += 32;
                cp16s(sb[st][i], pb[i]);  pb[i] += 16 * HW_;
            }
            CP_COMMIT();
        }
        const int bu = it % 3;
#pragma unroll
        for (int ks = 0; ks < 2; ks++) {
            unsigned af[4][4], bf[4][2];
#pragma unroll
            for (int mt = 0; mt < 4; mt++)
                ldsm_x4(af[mt], baseA[bu] + mt * (16 * A_STRIDE_B) + ks * 32);
#pragma unroll
            for (int nt = 0; nt < 4; nt++) {
                int cn = wn * 32 + nt * 8 + g;
                bf[nt][0] = h2u(S.u.ld.Bs[bu][ks * 8 + tg][cn]);
                bf[nt][1] = h2u(S.u.ld.Bs[bu][ks * 8 + tg + 4][cn]);
            }
#pragma unroll
            for (int mt = 0; mt < 4; mt++)
#pragma unroll
                for (int nt = 0; nt < 4; nt++)
                    mma_f16(acc[mt][nt], af[mt], bf[nt]);
        }
    }

    if (isQ) {
        // ---- q-softmax over d=32 (head = mt-pair; rows span g via shfl)
#pragma unroll
        for (int p = 0; p < 2; p++) {
#pragma unroll
            for (int nt = 0; nt < 4; nt++) {
#pragma unroll
                for (int j = 0; j < 2; j++) {
                    float v0 = acc[2 * p][nt][j],     v1 = acc[2 * p][nt][j + 2];
                    float v2 = acc[2 * p + 1][nt][j], v3 = acc[2 * p + 1][nt][j + 2];
                    float m = fmaxf(fmaxf(v0, v1), fmaxf(v2, v3));
                    m = fmaxf(m, __shfl_xor_sync(0xffffffffu, m, 4));
                    m = fmaxf(m, __shfl_xor_sync(0xffffffffu, m, 8));
                    m = fmaxf(m, __shfl_xor_sync(0xffffffffu, m, 16));
                    float e0 = __expf(v0 - m), e1 = __expf(v1 - m);
                    float e2 = __expf(v2 - m), e3 = __expf(v3 - m);
                    float s = e0 + e1 + e2 + e3;
                    s += __shfl_xor_sync(0xffffffffu, s, 4);
                    s += __shfl_xor_sync(0xffffffffu, s, 8);
                    s += __shfl_xor_sync(0xffffffffu, s, 16);
                    float inv = 1.0f / s;
                    acc[2 * p][nt][j]         = e0 * inv;
                    acc[2 * p][nt][j + 2]     = e1 * inv;
                    acc[2 * p + 1][nt][j]     = e2 * inv;
                    acc[2 * p + 1][nt][j + 2] = e3 * inv;
                }
            }
        }
        // ---- paired fp16 store: channel pairs (r0, r0+1) via shfl_xor(4)
#pragma unroll
        for (int mt = 0; mt < 4; mt++) {
            int r0 = m0 + wm * 64 + mt * 16 + g;
#pragma unroll
            for (int nt = 0; nt < 4; nt++) {
                float o0 = acc[mt][nt][0], o1 = acc[mt][nt][1];
                float o2 = acc[mt][nt][2], o3 = acc[mt][nt][3];
                float q0 = __shfl_xor_sync(0xffffffffu, o0, 4);
                float q1 = __shfl_xor_sync(0xffffffffu, o1, 4);
                float q2 = __shfl_xor_sync(0xffffffffu, o2, 4);
                float q3 = __shfl_xor_sync(0xffffffffu, o3, 4);
                if (!(g & 1)) {
                    int c = wn * 32 + nt * 8 + tg * 2;
                    __half2* d0 = &g_q2[((size_t)b * 128 + (r0 >> 1)) * HW_ + p0 + c];
                    d0[0] = __floats2half2_rn(o0, q0);
                    d0[1] = __floats2half2_rn(o1, q1);
                    __half2* d1 = d0 + (size_t)4 * HW_;     // rows r0+8, r0+9
                    d1[0] = __floats2half2_rn(o2, q2);
                    d1[1] = __floats2half2_rn(o3, q3);
                }
            }
        }
        return;
    }

    // ================= kv path =================
    // ---- k-softmax over y=64 (rows 0-63 -> wm==0 warps)
    float mloc[4][2], sloc[4][2];
    if (wm == 0) {
#pragma unroll
        for (int mt = 0; mt < 4; mt++)
#pragma unroll
            for (int hf = 0; hf < 2; hf++) {
                float m = -1e30f;
#pragma unroll
                for (int nt = 0; nt < 4; nt++) {
                    m = fmaxf(m, acc[mt][nt][hf * 2]);
                    m = fmaxf(m, acc[mt][nt][hf * 2 + 1]);
                }
                m = fmaxf(m, __shfl_xor_sync(0xffffffffu, m, 1));
                m = fmaxf(m, __shfl_xor_sync(0xffffffffu, m, 2));
                mloc[mt][hf] = m;
                if (tg == 0) S.red[0][wn][mt * 16 + hf * 8 + g] = m;
            }
    }
    __syncthreads();
    if (wm == 0) {
#pragma unroll
        for (int mt = 0; mt < 4; mt++)
#pragma unroll
            for (int hf = 0; hf < 2; hf++) {
                int ri = mt * 16 + hf * 8 + g;
                float m = fmaxf(mloc[mt][hf], S.red[0][wn ^ 1][ri]);
                float s = 0.f;
#pragma unroll
                for (int nt = 0; nt < 4; nt++) {
                    float e0 = __expf(acc[mt][nt][hf * 2] - m);
                    float e1 = __expf(acc[mt][nt][hf * 2 + 1] - m);
                    acc[mt][nt][hf * 2]     = e0;
                    acc[mt][nt][hf * 2 + 1] = e1;
                    s += e0 + e1;
                }
                s += __shfl_xor_sync(0xffffffffu, s, 1);
                s += __shfl_xor_sync(0xffffffffu, s, 2);
                sloc[mt][hf] = s;
                if (tg == 0) S.red[1][wn][ri] = s;
            }
    }
    __syncthreads();
    if (wm == 0) {
#pragma unroll
        for (int mt = 0; mt < 4; mt++)
#pragma unroll
            for (int hf = 0; hf < 2; hf++) {
                int ri = mt * 16 + hf * 8 + g;
                float inv = 1.0f / (sloc[mt][hf] + S.red[1][wn ^ 1][ri]);
#pragma unroll
                for (int nt = 0; nt < 4; nt++) {
                    acc[mt][nt][hf * 2]     *= inv;
                    acc[mt][nt][hf * 2 + 1] *= inv;
                }
            }
    }
    __syncthreads();

    // ---- store sc[row][pixel] as fp16 (half2 per pixel pair)
#pragma unroll
    for (int mt = 0; mt < 4; mt++) {
        int r0 = wm * 64 + mt * 16 + g;
#pragma unroll
        for (int nt = 0; nt < 4; nt++) {
            int c = wn * 32 + nt * 8 + tg * 2;
            *(__half2*)&S.sc[r0][c]     = __floats2half2_rn(acc[mt][nt][0], acc[mt][nt][1]);
            *(__half2*)&S.sc[r0 + 8][c] = __floats2half2_rn(acc[mt][nt][2], acc[mt][nt][3]);
        }
    }
    __syncthreads();

    // ---- ctx partial via fp16 MMA: per warp M=32(d) x N=32(e) x K=32(p)
    {
        const int h  = warp >> 2, hb = h * 32;
        const int pb0 = (warp & 3) * 32;
        float cacc[2][4][4] = {};
#pragma unroll
        for (int ks = 0; ks < 2; ks++) {
            const int pw = pb0 + ks * 16;
            unsigned af[2][4], bf[4][2];
#pragma unroll
            for (int mt = 0; mt < 2; mt++) {
                int dm = hb + mt * 16 + g;
                af[mt][0] = *(const unsigned*)&S.sc[dm][pw + 2 * tg];
                af[mt][1] = *(const unsigned*)&S.sc[dm + 8][pw + 2 * tg];
                af[mt][2] = *(const unsigned*)&S.sc[dm][pw + 2 * tg + 8];
                af[mt][3] = *(const unsigned*)&S.sc[dm + 8][pw + 2 * tg + 8];
            }
#pragma unroll
            for (int nt = 0; nt < 4; nt++) {
                int en = 64 + hb + nt * 8 + g;
                bf[nt][0] = *(const unsigned*)&S.sc[en][pw + 2 * tg];
                bf[nt][1] = *(const unsigned*)&S.sc[en][pw + 2 * tg + 8];
            }
#pragma unroll
            for (int mt = 0; mt < 2; mt++)
#pragma unroll
                for (int nt = 0; nt < 4; nt++)
                    mma_f16(cacc[mt][nt], af[mt], bf[nt]);
        }
#pragma unroll
        for (int mt = 0; mt < 2; mt++) {
            int d = mt * 16 + g;
#pragma unroll
            for (int nt = 0; nt < 4; nt++) {
                int e = nt * 8 + tg * 2;
                S.u.P[warp][d][e]         = cacc[mt][nt][0];
                S.u.P[warp][d][e + 1]     = cacc[mt][nt][1];
                S.u.P[warp][d + 8][e]     = cacc[mt][nt][2];
                S.u.P[warp][d + 8][e + 1] = cacc[mt][nt][3];
            }
        }
    }
    __syncthreads();

    // ---- reduce 4 K-slices per head, write ctx partial
    {
        float* op = g_ctxp + (((size_t)(b * HEADS_ + hp * 2)) * 32 + pt) * (D_ * D_);
#pragma unroll
        for (int i = 0; i < 8; i++) {
            int elem = tid + i * 256;
            int hh = elem >> 10;
            int de = elem & 1023;
            int d = de >> 5, e = de & 31;
            float s = S.u.P[hh * 4 + 0][d][e] + S.u.P[hh * 4 + 1][d][e]
                    + S.u.P[hh * 4 + 2][d][e] + S.u.P[hh * 4 + 3][d][e];
            op[(size_t)hh * 32 * (D_ * D_) + de] = s;
        }
    }
}

// =====================================================================
// Kernel 2: reduce ctx partials + w_eff = w_out @ ctx -> fp16. 512 threads.
// (round-15 proven version)
// =====================================================================
__global__ void __launch_bounds__(512) k_weff(const float* __restrict__ w_out) {
    const int h = blockIdx.x, b = blockIdx.y;
    const int bh = b * HEADS_ + h;
    const int t = threadIdx.x;

    __shared__ float ctxs[32][36];
    __shared__ float ws[256][33];

    {
        const float2* pp2 = (const float2*)(g_ctxp + (size_t)bh * 32 * (D_ * D_));
        float2 s0 = make_float2(0.f, 0.f), s1 = s0, s2 = s0, s3 = s0;
#pragma unroll
        for (int pg = 0; pg < 32; pg += 4) {
            float2 v0 = pp2[(pg + 0) * 512 + t];
            float2 v1 = pp2[(pg + 1) * 512 + t];
            float2 v2 = pp2[(pg + 2) * 512 + t];
            float2 v3 = pp2[(pg + 3) * 512 + t];
            s0.x += v0.x; s0.y += v0.y;
            s1.x += v1.x; s1.y += v1.y;
            s2.x += v2.x; s2.y += v2.y;
            s3.x += v3.x; s3.y += v3.y;
        }
        float2 s = make_float2(s0.x + s1.x + s2.x + s3.x, s0.y + s1.y + s2.y + s3.y);
        int elem = t * 2;
        *(float2*)&ctxs[elem >> 5][elem & 31] = s;
    }
#pragma unroll
    for (int i = 0; i < 16; i++) {
        int idx = t + i * 512;
        int r = idx >> 5, c = idx & 31;
        ws[r][c] = w_out[(size_t)r * C_ + h * D_ + c];
    }
    __syncthreads();

    if (t < 256) {
        float we[32] = {};
#pragma unroll
        for (int d = 0; d < 32; d++) {
            float wv = ws[t][d];
#pragma unroll
            for (int e = 0; e < 32; e++) we[e] += wv * ctxs[d][e];
        }
        __half* op = g_weffh + ((size_t)b * C_ + t) * C_ + h * D_;
#pragma unroll
        for (int e2 = 0; e2 < 16; e2++)
            *(__half2*)&op[e2 * 2] = __floats2half2_rn(we[e2 * 2], we[e2 * 2 + 1]);
    }
}

// =====================================================================
// Kernel 3: out = w_eff[b] @ qhat + b_out, fused channel LayerNorm.
// fp16 MMA; M=256 x N=128 tile, 512 threads (16 warps 4x4); 3-stage pipe.
// =====================================================================
__global__ void __launch_bounds__(512) k_out_ln(const float* __restrict__ b_out,
                                                const float* __restrict__ gamma,
                                                const float* __restrict__ beta,
                                                float* __restrict__ out) {
    extern __shared__ char smem_raw[];
    OutSmem& S = *reinterpret_cast<OutSmem*>(smem_raw);

    const int tid  = threadIdx.x;
    const int warp = tid >> 5, lane = tid & 31;
    const int g = lane >> 2, tg = lane & 3;
    const int wm = warp >> 2, wn = warp & 3;     // 4 x 4 warp grid

    const int blk = blockIdx.x;
    const int b   = blk >> 5;                    // 32 pixel-tiles per batch
    const int p0  = (blk & 31) * 128;

    if (tid < 128) { S.s_sum[tid] = 0.f; S.s_sq[tid] = 0.f; }

    const __half* pa[2]; const __half2* pb;
    unsigned sa[3][2], sb[3];
#pragma unroll
    for (int i = 0; i < 2; i++) {
        int f4 = tid + i * 512;
        int ra = f4 >> 2, ca = (f4 & 3) * 8;
        pa[i] = g_weffh + (size_t)b * C_ * C_ + (size_t)ra * C_ + ca;
#pragma unroll
        for (int s = 0; s < 3; s++) sa[s][i] = s2u(&S.As[s][ra][ca]);
    }
    {
        int rb = tid >> 5, cb = (tid & 31) * 4;
        pb = g_q2 + ((size_t)b * 128 + rb) * HW_ + p0 + cb;
#pragma unroll
        for (int s = 0; s < 3; s++) sb[s] = s2u(&S.Bs[s][rb][cb]);
    }

    const int lmRow = wm * 64 + (lane & 15);
    const int lmCol = (lane >> 4) * 8;
    unsigned baseA[3];
#pragma unroll
    for (int s = 0; s < 3; s++) baseA[s] = s2u(&S.As[s][lmRow][lmCol]);

    float acc[4][4][4] = {};

#pragma unroll
    for (int s = 0; s < 2; s++) {
#pragma unroll
        for (int i = 0; i < 2; i++) { cp16s(sa[s][i], pa[i]); pa[i] += 32; }
        cp16s(sb[s], pb); pb += 16 * HW_;
        CP_COMMIT();
    }

#pragma unroll
    for (int it = 0; it < 8; it++) {
        if (it < 7) { CP_WAIT(1); } else { CP_WAIT(0); }
        __syncthreads();
        if (it < 6) {
            const int st = (it + 2) % 3;
#pragma unroll
            for (int i = 0; i < 2; i++) { cp16s(sa[st][i], pa[i]); pa[i] += 32; }
            cp16s(sb[st], pb); pb += 16 * HW_;
            CP_COMMIT();
        }
        const int bu = it % 3;
#pragma unroll
        for (int ks = 0; ks < 2; ks++) {
            unsigned af[4][4], bf[4][2];
#pragma unroll
            for (int mt = 0; mt < 4; mt++)
                ldsm_x4(af[mt], baseA[bu] + mt * (16 * A_STRIDE_B) + ks * 32);
#pragma unroll
            for (int nt = 0; nt < 4; nt++) {
                int cn = wn * 32 + nt * 8 + g;
                bf[nt][0] = h2u(S.Bs[bu][ks * 8 + tg][cn]);
                bf[nt][1] = h2u(S.Bs[bu][ks * 8 + tg + 4][cn]);
            }
#pragma unroll
            for (int mt = 0; mt < 4; mt++)
#pragma unroll
                for (int nt = 0; nt < 4; nt++)
                    mma_f16(acc[mt][nt], af[mt], bf[nt]);
        }
    }

    float bias0[4], bias1[4], gam0[4], gam1[4], bet0[4], bet1[4];
#pragma unroll
    for (int mt = 0; mt < 4; mt++) {
        int r = wm * 64 + mt * 16 + g;
        bias0[mt] = b_out[r]; bias1[mt] = b_out[r + 8];
        gam0[mt]  = gamma[r]; gam1[mt]  = gamma[r + 8];
        bet0[mt]  = beta[r];  bet1[mt]  = beta[r + 8];
    }
#pragma unroll
    for (int mt = 0; mt < 4; mt++)
#pragma unroll
        for (int nt = 0; nt < 4; nt++) {
            acc[mt][nt][0] += bias0[mt]; acc[mt][nt][1] += bias0[mt];
            acc[mt][nt][2] += bias1[mt]; acc[mt][nt][3] += bias1[mt];
        }

#pragma unroll
    for (int nt = 0; nt < 4; nt++) {
        float s0 = 0.f, s1 = 0.f, q0 = 0.f, q1 = 0.f;
#pragma unroll
        for (int mt = 0; mt < 4; mt++) {
            float v0 = acc[mt][nt][0], v1 = acc[mt][nt][1];
            float v2 = acc[mt][nt][2], v3 = acc[mt][nt][3];
            s0 += v0 + v2; s1 += v1 + v3;
            q0 += v0 * v0 + v2 * v2; q1 += v1 * v1 + v3 * v3;
        }
#pragma unroll
        for (int off = 4; off < 32; off <<= 1) {
            s0 += __shfl_xor_sync(0xffffffffu, s0, off);
            s1 += __shfl_xor_sync(0xffffffffu, s1, off);
            q0 += __shfl_xor_sync(0xffffffffu, q0, off);
            q1 += __shfl_xor_sync(0xffffffffu, q1, off);
        }
        if (g == 0) {
            int c = wn * 32 + nt * 8 + tg * 2;
            atomicAdd(&S.s_sum[c], s0);     atomicAdd(&S.s_sq[c], q0);
            atomicAdd(&S.s_sum[c + 1], s1); atomicAdd(&S.s_sq[c + 1], q1);
        }
    }
    __syncthreads();

    if (tid < 128) {
        float mu  = S.s_sum[tid] * (1.0f / 256.0f);
        float var = S.s_sq[tid] * (1.0f / 256.0f) - mu * mu;
        S.s_mu[tid] = mu;
        S.s_rs[tid] = rsqrtf(var + LN_EPS);
    }
    __syncthreads();

    float* ob = out + (size_t)b * (C_ * HW_) + p0;
#pragma unroll
    for (int mt = 0; mt < 4; mt++) {
        int r = wm * 64 + mt * 16 + g;
#pragma unroll
        for (int nt = 0; nt < 4; nt++) {
            int c = wn * 32 + nt * 8 + tg * 2;
            float mu0 = S.s_mu[c], rs0 = S.s_rs[c];
            float mu1 = S.s_mu[c + 1], rs1 = S.s_rs[c + 1];
            float o0 = (acc[mt][nt][0] - mu0) * rs0 * gam0[mt] + bet0[mt];
            float o1 = (acc[mt][nt][1] - mu1) * rs1 * gam0[mt] + bet0[mt];
            float o2 = (acc[mt][nt][2] - mu0) * rs0 * gam1[mt] + bet1[mt];
            float o3 = (acc[mt][nt][3] - mu1) * rs1 * gam1[mt] + bet1[mt];
            *(float2*)&ob[(size_t)r * HW_ + c]       = make_float2(o0, o1);
            *(float2*)&ob[(size_t)(r + 8) * HW_ + c] = make_float2(o2, o3);
        }
    }
}

// =====================================================================
extern "C" void kernel_launch(void* const* d_in, const int* in_sizes, int n_in,
                              void* d_out, int out_size) {
    const float* x      = (const float*)d_in[0];
    const float* w_qkv  = (const float*)d_in[1];
    const float* w_out  = (const float*)d_in[2];
    const float* b_out  = (const float*)d_in[3];
    const float* gamma  = (const float*)d_in[4];
    const float* beta   = (const float*)d_in[5];
    float* out = (float*)d_out;

    cudaFuncSetAttribute(k_main, cudaFuncAttributeMaxDynamicSharedMemorySize,
                         (int)sizeof(MainSmem));
    cudaFuncSetAttribute(k_out_ln, cudaFuncAttributeMaxDynamicSharedMemorySize,
                         (int)sizeof(OutSmem));

    k_pre<<<8192 + 192, 256>>>(x, w_qkv);                 // x pack + w convert

    k_main<<<2048 + 1024, 256, sizeof(MainSmem)>>>();     // kv blocks first, q last

    dim3 g3(HEADS_, B_);                                  // 8 x 16
    k_weff<<<g3, 512>>>(w_out);

    k_out_ln<<<(B_ * HW_) / 128, 512, sizeof(OutSmem)>>>(b_out, gamma, beta, out);
}